// round 4
// baseline (speedup 1.0000x reference)
#include <cuda_runtime.h>
#include <cstdint>

#define NWIN 64
#define HN 8
#define NQ 49
#define MT 50
#define BWIN 4096
#define DIM 256
#define SCALE 0.17677669529663689f

// Precombined (mask + relative position bias) table: [w][h][qi][j], ~5 MB, L2-resident.
__device__ float g_bm[NWIN * HN * NQ * MT];

__global__ void precompute_bm_kernel(const float* __restrict__ mask,
                                     const float* __restrict__ bias_table,
                                     const int* __restrict__ rel_index) {
    int i = blockIdx.x * blockDim.x + threadIdx.x;
    if (i >= NWIN * HN * NQ * MT) return;
    int j  = i % MT;
    int r  = i / MT;
    int qi = r % NQ; r /= NQ;
    int h  = r % HN;
    int w  = r / HN;
    float v = mask[(w * NQ + qi) * MT + j];
    if (j > 0) {
        int idx = rel_index[qi * NQ + (j - 1)];
        v += bias_table[idx * HN + h];
    }
    g_bm[i] = v;
}

__device__ __forceinline__ uint32_t f2tf(float f) {
    uint32_t r;
    asm("cvt.rna.tf32.f32 %0, %1;" : "=r"(r) : "f"(f));
    return r;
}

__device__ __forceinline__ void mma_tf32(float c[4], const uint32_t a[4],
                                         uint32_t b0, uint32_t b1) {
    asm volatile(
        "mma.sync.aligned.m16n8k8.row.col.f32.tf32.tf32.f32 "
        "{%0,%1,%2,%3}, {%4,%5,%6,%7}, {%8,%9}, {%0,%1,%2,%3};"
        : "+f"(c[0]), "+f"(c[1]), "+f"(c[2]), "+f"(c[3])
        : "r"(a[0]), "r"(a[1]), "r"(a[2]), "r"(a[3]), "r"(b0), "r"(b1));
}

// One CTA per (window, head). 4 warps; warp w owns query rows 16w + {g, g+8}.
// QK^T via 3xTF32 (error-compensated) mma.sync, softmax in fragments (no max pass),
// P staged through smem into A-fragment layout, PV via plain tf32 mma.sync.
__global__ void __launch_bounds__(128)
window_attn_mma(const float* __restrict__ qkv, float* __restrict__ out) {
    const int bh = blockIdx.x;
    const int b  = bh >> 3;
    const int h  = bh & 7;
    const int w  = b & (NWIN - 1);

    // Bank-conflict-tuned strides: 36 (q: g*36 mod32 = 4g), 56 (kT: t*56 mod32 = 24t),
    // 40 (v: t*40 mod32 = 8t), 60 (p: g*60 mod32 = 28g) — all fragment loads conflict-free.
    __shared__ float    s_q[64][36];     // fp32 queries (pre-scaled), rows >=49 zeroed
    __shared__ float    s_kT[32][56];    // fp32 K transposed [d][key], keys >=50 zeroed
    __shared__ uint32_t s_v[56][40];     // tf32 V [key][d], keys >=50 zeroed
    __shared__ uint32_t s_p[4][16][60];  // per-warp tf32 P tile (16 x 56)

    const float* base = qkv + (size_t)b * MT * 768;
    const int tid = threadIdx.x;

    // ---- stage Q (scaled, zero-padded rows) ----
    for (int i = tid; i < 64 * 32; i += 128) {
        int m = i >> 5, d = i & 31;
        float v = 0.f;
        if (m < NQ) v = base[(m + 1) * 768 + h * 32 + d] * SCALE;
        s_q[m][d] = v;
    }
    // ---- stage K transposed (fp32; hi/lo split happens at fragment load) ----
    for (int i = tid; i < 56 * 32; i += 128) {
        int key = i >> 5, d = i & 31;
        float v = 0.f;
        if (key < MT) v = base[key * 768 + 256 + h * 32 + d];
        s_kT[d][key] = v;
    }
    // ---- stage V (tf32, zero-padded rows) ----
    for (int i = tid; i < 56 * 32; i += 128) {
        int key = i >> 5, d = i & 31;
        float v = 0.f;
        if (key < MT) v = base[key * 768 + 512 + h * 32 + d];
        s_v[key][d] = f2tf(v);
    }
    __syncthreads();

    const int warp = tid >> 5, lane = tid & 31;
    const int g = lane >> 2, t = lane & 3;
    const int qrow = warp * 16 + g;  // second row: qrow + 8

    // ---- A fragments (q) with hi/lo split for 3xTF32 ----
    uint32_t ahi[4][4], alo[4][4];
    #pragma unroll
    for (int kc = 0; kc < 4; kc++) {
        float f0 = s_q[qrow][t + 8 * kc];
        float f1 = s_q[qrow + 8][t + 8 * kc];
        float f2 = s_q[qrow][t + 4 + 8 * kc];
        float f3 = s_q[qrow + 8][t + 4 + 8 * kc];
        ahi[kc][0] = f2tf(f0); alo[kc][0] = f2tf(f0 - __uint_as_float(ahi[kc][0]));
        ahi[kc][1] = f2tf(f1); alo[kc][1] = f2tf(f1 - __uint_as_float(ahi[kc][1]));
        ahi[kc][2] = f2tf(f2); alo[kc][2] = f2tf(f2 - __uint_as_float(ahi[kc][2]));
        ahi[kc][3] = f2tf(f3); alo[kc][3] = f2tf(f3 - __uint_as_float(ahi[kc][3]));
    }

    // ---- QK^T: 7 n-tiles x 4 k-chunks x 3 compensated MMAs ----
    float c[7][4];
    #pragma unroll
    for (int nt = 0; nt < 7; nt++)
        c[nt][0] = c[nt][1] = c[nt][2] = c[nt][3] = 0.f;

    #pragma unroll
    for (int nt = 0; nt < 7; nt++) {
        #pragma unroll
        for (int kc = 0; kc < 4; kc++) {
            float b0f = s_kT[8 * kc + t][8 * nt + g];
            float b1f = s_kT[8 * kc + t + 4][8 * nt + g];
            uint32_t bh0 = f2tf(b0f), bl0 = f2tf(b0f - __uint_as_float(bh0));
            uint32_t bh1 = f2tf(b1f), bl1 = f2tf(b1f - __uint_as_float(bh1));
            mma_tf32(c[nt], ahi[kc], bh0, bh1);  // hi*hi
            mma_tf32(c[nt], alo[kc], bh0, bh1);  // lo*hi
            mma_tf32(c[nt], ahi[kc], bl0, bl1);  // hi*lo
        }
    }

    // ---- add (mask + bias), exp (no max pass: logits bounded), row sums ----
    const int qa = (qrow < NQ) ? qrow : (NQ - 1);
    const int qb = (qrow + 8 < NQ) ? (qrow + 8) : (NQ - 1);
    const float* bmA = g_bm + ((size_t)(w * HN + h) * NQ + qa) * MT;
    const float* bmB = g_bm + ((size_t)(w * HN + h) * NQ + qb) * MT;

    float sum0 = 0.f, sum1 = 0.f;
    #pragma unroll
    for (int nt = 0; nt < 7; nt++) {
        int col = 8 * nt + 2 * t;
        if (col <= MT - 2) {
            float2 mA = *(const float2*)(bmA + col);
            float2 mB = *(const float2*)(bmB + col);
            c[nt][0] += mA.x; c[nt][1] += mA.y;
            c[nt][2] += mB.x; c[nt][3] += mB.y;
        } else {  // padded key columns (50..55): force prob to 0
            c[nt][0] = c[nt][1] = c[nt][2] = c[nt][3] = -1e30f;
        }
        c[nt][0] = __expf(c[nt][0]);
        c[nt][1] = __expf(c[nt][1]);
        c[nt][2] = __expf(c[nt][2]);
        c[nt][3] = __expf(c[nt][3]);
        sum0 += c[nt][0] + c[nt][1];
        sum1 += c[nt][2] + c[nt][3];
    }
    sum0 += __shfl_xor_sync(0xffffffffu, sum0, 1);
    sum0 += __shfl_xor_sync(0xffffffffu, sum0, 2);
    sum1 += __shfl_xor_sync(0xffffffffu, sum1, 1);
    sum1 += __shfl_xor_sync(0xffffffffu, sum1, 2);
    const float inv0 = 1.0f / sum0;
    const float inv1 = 1.0f / sum1;

    // ---- normalize, convert to tf32, write P to smem in A-load-friendly layout ----
    #pragma unroll
    for (int nt = 0; nt < 7; nt++) {
        int col = 8 * nt + 2 * t;
        uint2 pA, pB;
        pA.x = f2tf(c[nt][0] * inv0); pA.y = f2tf(c[nt][1] * inv0);
        pB.x = f2tf(c[nt][2] * inv1); pB.y = f2tf(c[nt][3] * inv1);
        *(uint2*)&s_p[warp][g][col]     = pA;
        *(uint2*)&s_p[warp][g + 8][col] = pB;
    }
    __syncwarp();

    // ---- PV: 7 k-chunks x 4 n-tiles, plain tf32 ----
    float o[4][4];
    #pragma unroll
    for (int nt = 0; nt < 4; nt++)
        o[nt][0] = o[nt][1] = o[nt][2] = o[nt][3] = 0.f;

    #pragma unroll
    for (int kc = 0; kc < 7; kc++) {
        uint32_t a[4];
        a[0] = s_p[warp][g][t + 8 * kc];
        a[1] = s_p[warp][g + 8][t + 8 * kc];
        a[2] = s_p[warp][g][t + 4 + 8 * kc];
        a[3] = s_p[warp][g + 8][t + 4 + 8 * kc];
        #pragma unroll
        for (int nt = 0; nt < 4; nt++) {
            uint32_t b0 = s_v[8 * kc + t][8 * nt + g];
            uint32_t b1 = s_v[8 * kc + t + 4][8 * nt + g];
            mma_tf32(o[nt], a, b0, b1);
        }
    }

    // ---- store: out[b][qi][h*32 + d] ----
    if (qrow < NQ) {
        float* orow = out + ((size_t)b * NQ + qrow) * DIM + h * 32;
        #pragma unroll
        for (int nt = 0; nt < 4; nt++) {
            float2 v2; v2.x = o[nt][0]; v2.y = o[nt][1];
            *(float2*)(orow + 8 * nt + 2 * t) = v2;
        }
    }
    if (qrow + 8 < NQ) {
        float* orow = out + ((size_t)b * NQ + qrow + 8) * DIM + h * 32;
        #pragma unroll
        for (int nt = 0; nt < 4; nt++) {
            float2 v2; v2.x = o[nt][2]; v2.y = o[nt][3];
            *(float2*)(orow + 8 * nt + 2 * t) = v2;
        }
    }
}

extern "C" void kernel_launch(void* const* d_in, const int* in_sizes, int n_in,
                              void* d_out, int out_size) {
    const float* qkv        = (const float*)d_in[0];
    const float* mask       = (const float*)d_in[1];
    const float* bias_table = (const float*)d_in[2];
    const int*   rel_index  = (const int*)d_in[3];
    float* out = (float*)d_out;

    const int total = NWIN * HN * NQ * MT;
    precompute_bm_kernel<<<(total + 255) / 256, 256>>>(mask, bias_table, rel_index);
    window_attn_mma<<<BWIN * HN, 128>>>(qkv, out);
}

// round 5
// speedup vs baseline: 1.4473x; 1.4473x over previous
#include <cuda_runtime.h>
#include <cstdint>

#define NWIN 64
#define HN 8
#define NQ 49
#define NQP 52      // padded qi stride for the transposed bias table
#define MT 50
#define BWIN 4096
#define DIM 256
#define SCALE 0.17677669529663689f

// Transposed precombined (mask + rel-pos bias) table: [w][h][j][qi(pad 52)], ~5.3 MB.
// Lane-coalesced reads in the main loop (lane index = qi).
__device__ float g_bmT[NWIN * HN * MT * NQP];

__global__ void precompute_bmT(const float* __restrict__ mask,
                               const float* __restrict__ bias_table,
                               const int* __restrict__ rel_index) {
    int i = blockIdx.x * blockDim.x + threadIdx.x;
    if (i >= NWIN * HN * MT * NQP) return;
    int r = i % NQP;
    int j = (i / NQP) % MT;
    int h = (i / (NQP * MT)) % HN;
    int w = i / (NQP * MT * HN);
    float v = 0.f;
    if (r < NQ) {
        v = mask[(w * NQ + r) * MT + j];
        if (j > 0) v += bias_table[rel_index[r * NQ + (j - 1)] * HN + h];
    }
    g_bmT[i] = v;
}

// ---- packed f32x2 helpers (sm_103a) ----
#define PACK2(d, lo, hi)   asm("mov.b64 %0, {%1, %2};" : "=l"(d) : "r"(lo), "r"(hi))
#define UNPACK2(lo, hi, s) asm("mov.b64 {%0, %1}, %2;" : "=r"(lo), "=r"(hi) : "l"(s))
#define FMA2(d, a, b, c)   asm("fma.rn.f32x2 %0, %1, %2, %3;" : "=l"(d) : "l"(a), "l"(b), "l"(c))
#define MUL2(d, a, b)      asm("mul.rn.f32x2 %0, %1, %2;" : "=l"(d) : "l"(a), "l"(b))
#define ADD2(d, a, b)      asm("add.rn.f32x2 %0, %1, %2;" : "=l"(d) : "l"(a), "l"(b))
#define LDSV2(a, b, addr)  asm volatile("ld.shared.v2.b64 {%0, %1}, [%2];" : "=l"(a), "=l"(b) : "r"(addr))

// One warp per (window, head); lanes 0-24 each own TWO query rows {l, l+25}.
// Fused QK -> exp -> PV per key token (no softmax max pass: logits bounded).
// CTA = 64 threads = 2 warps = 2 heads of one window (25.6 KB k/v staging).
__global__ void __launch_bounds__(64)
window_attn_fused(const float* __restrict__ qkv, float* __restrict__ out) {
    const int cta = blockIdx.x;
    const int b = cta >> 2;                 // window index
    const int head_base = (cta & 3) << 1;   // 2 heads per CTA
    const int w = b & (NWIN - 1);

    __shared__ float4 s_kv[2][2][MT][8];    // [k/v][local head][token][16B chunk]

    const float* base = qkv + (size_t)b * MT * 768;
    const int tid = threadIdx.x;

    // Stage K and V for this CTA's 2 heads (coalesced float4 loads).
    for (int i = tid; i < 2 * MT * 8; i += 64) {
        int m = i >> 4;              // token
        int hh = (i >> 3) & 1;       // local head
        int c = i & 7;               // 16B chunk within the 32-float head slice
        const float* row = base + m * 768 + (head_base + hh) * 32 + c * 4;
        s_kv[0][hh][m][c] = *(const float4*)(row + 256);
        s_kv[1][hh][m][c] = *(const float4*)(row + 512);
    }
    __syncthreads();

    const int warp = tid >> 5, lane = tid & 31;
    const int h = head_base + warp;
    const int r0 = (lane < 25) ? lane : 24;        // clamped dup for idle lanes
    const int r1 = (lane < 24) ? (lane + 25) : 48;

    // Load both q rows into packed f32x2 registers, pre-scaled.
    unsigned long long q0[16], q1[16];
    {
        const ulonglong2* p0 = (const ulonglong2*)(base + (r0 + 1) * 768 + h * 32);
        const ulonglong2* p1 = (const ulonglong2*)(base + (r1 + 1) * 768 + h * 32);
        #pragma unroll
        for (int i = 0; i < 8; i++) {
            ulonglong2 a = p0[i]; q0[2 * i] = a.x; q0[2 * i + 1] = a.y;
            ulonglong2 c2 = p1[i]; q1[2 * i] = c2.x; q1[2 * i + 1] = c2.y;
        }
        unsigned su = __float_as_uint(SCALE);
        unsigned long long s2; PACK2(s2, su, su);
        #pragma unroll
        for (int i = 0; i < 16; i++) { MUL2(q0[i], q0[i], s2); MUL2(q1[i], q1[i], s2); }
    }

    const unsigned kb = (unsigned)__cvta_generic_to_shared(&s_kv[0][warp][0][0]);
    const unsigned vb = (unsigned)__cvta_generic_to_shared(&s_kv[1][warp][0][0]);
    const float* bmh = g_bmT + (size_t)(w * HN + h) * MT * NQP;

    unsigned long long o0[16], o1[16];
    #pragma unroll
    for (int i = 0; i < 16; i++) { o0[i] = 0ull; o1[i] = 0ull; }
    float s0 = 0.f, s1 = 0.f;

    #pragma unroll 2
    for (int j = 0; j < MT; j++) {
        const unsigned ka = kb + j * 128;
        unsigned long long kt[8];
        unsigned long long a[4], c[4];

        // --- QK dot products for both rows (k row broadcast from smem) ---
        #pragma unroll
        for (int cc = 0; cc < 4; cc++) LDSV2(kt[2 * cc], kt[2 * cc + 1], ka + cc * 16);
        #pragma unroll
        for (int i = 0; i < 4; i++) { MUL2(a[i], q0[i], kt[i]); MUL2(c[i], q1[i], kt[i]); }
        #pragma unroll
        for (int i = 4; i < 8; i++) {
            FMA2(a[i - 4], q0[i], kt[i], a[i - 4]);
            FMA2(c[i - 4], q1[i], kt[i], c[i - 4]);
        }
        #pragma unroll
        for (int cc = 0; cc < 4; cc++) LDSV2(kt[2 * cc], kt[2 * cc + 1], ka + 64 + cc * 16);
        #pragma unroll
        for (int i = 0; i < 8; i++) {
            FMA2(a[i & 3], q0[8 + i], kt[i], a[i & 3]);
            FMA2(c[i & 3], q1[8 + i], kt[i], c[i & 3]);
        }
        ADD2(a[0], a[0], a[1]); ADD2(a[2], a[2], a[3]); ADD2(a[0], a[0], a[2]);
        ADD2(c[0], c[0], c[1]); ADD2(c[2], c[2], c[3]); ADD2(c[0], c[0], c[2]);
        unsigned lo, hi;
        UNPACK2(lo, hi, a[0]);
        float d0 = __uint_as_float(lo) + __uint_as_float(hi);
        UNPACK2(lo, hi, c[0]);
        float d1 = __uint_as_float(lo) + __uint_as_float(hi);

        // --- bias+mask (lane-coalesced), exp (no max pass), running sums ---
        float e0 = __expf(d0 + bmh[j * NQP + r0]);
        float e1 = __expf(d1 + bmh[j * NQP + r1]);
        s0 += e0; s1 += e1;

        // --- PV accumulation (v row broadcast from smem) ---
        unsigned long long e0p, e1p;
        { unsigned eu = __float_as_uint(e0); PACK2(e0p, eu, eu); }
        { unsigned eu = __float_as_uint(e1); PACK2(e1p, eu, eu); }
        const unsigned va = vb + j * 128;
        unsigned long long vt[8];
        #pragma unroll
        for (int cc = 0; cc < 4; cc++) LDSV2(vt[2 * cc], vt[2 * cc + 1], va + cc * 16);
        #pragma unroll
        for (int i = 0; i < 8; i++) {
            FMA2(o0[i], e0p, vt[i], o0[i]);
            FMA2(o1[i], e1p, vt[i], o1[i]);
        }
        #pragma unroll
        for (int cc = 0; cc < 4; cc++) LDSV2(vt[2 * cc], vt[2 * cc + 1], va + 64 + cc * 16);
        #pragma unroll
        for (int i = 0; i < 8; i++) {
            FMA2(o0[8 + i], e0p, vt[i], o0[8 + i]);
            FMA2(o1[8 + i], e1p, vt[i], o1[8 + i]);
        }
    }

    // Normalize once at the end.
    {
        unsigned iu = __float_as_uint(1.0f / s0);
        unsigned long long inv2; PACK2(inv2, iu, iu);
        #pragma unroll
        for (int i = 0; i < 16; i++) MUL2(o0[i], o0[i], inv2);
    }
    {
        unsigned iu = __float_as_uint(1.0f / s1);
        unsigned long long inv2; PACK2(inv2, iu, iu);
        #pragma unroll
        for (int i = 0; i < 16; i++) MUL2(o1[i], o1[i], inv2);
    }

    if (lane < 25) {
        ulonglong2* orow = (ulonglong2*)(out + ((size_t)b * NQ + r0) * DIM + h * 32);
        #pragma unroll
        for (int i = 0; i < 8; i++) {
            ulonglong2 v2; v2.x = o0[2 * i]; v2.y = o0[2 * i + 1];
            orow[i] = v2;
        }
    }
    if (lane < 24) {
        ulonglong2* orow = (ulonglong2*)(out + ((size_t)b * NQ + r1) * DIM + h * 32);
        #pragma unroll
        for (int i = 0; i < 8; i++) {
            ulonglong2 v2; v2.x = o1[2 * i]; v2.y = o1[2 * i + 1];
            orow[i] = v2;
        }
    }
}

extern "C" void kernel_launch(void* const* d_in, const int* in_sizes, int n_in,
                              void* d_out, int out_size) {
    const float* qkv        = (const float*)d_in[0];
    const float* mask       = (const float*)d_in[1];
    const float* bias_table = (const float*)d_in[2];
    const int*   rel_index  = (const int*)d_in[3];
    float* out = (float*)d_out;

    const int total = NWIN * HN * MT * NQP;
    precompute_bmT<<<(total + 255) / 256, 256>>>(mask, bias_table, rel_index);
    window_attn_fused<<<BWIN * HN / 2, 64>>>(qkv, out);
}

// round 10
// speedup vs baseline: 2.8481x; 1.9679x over previous
#include <cuda_runtime.h>
#include <cstdint>

#define NWIN 64
#define HN 8
#define NQ 49
#define MT 50
#define BWIN 4096
#define DIM 256
#define SCALE 0.17677669529663689f

// Precombined (mask + relative position bias) table: [w][h][qi][j], ~5 MB, L2-resident.
__device__ float g_bm[NWIN * HN * NQ * MT];

__global__ void precompute_bm_kernel(const float* __restrict__ mask,
                                     const float* __restrict__ bias_table,
                                     const int* __restrict__ rel_index) {
    int i = blockIdx.x * blockDim.x + threadIdx.x;
    if (i >= NWIN * HN * NQ * MT) return;
    int j  = i % MT;
    int r  = i / MT;
    int qi = r % NQ; r /= NQ;
    int h  = r % HN;
    int w  = r / HN;
    float v = mask[(w * NQ + qi) * MT + j];
    if (j > 0) {
        int idx = rel_index[qi * NQ + (j - 1)];
        v += bias_table[idx * HN + h];
    }
    g_bm[i] = v;
}

__device__ __forceinline__ uint32_t f2tf(float f) {
    uint32_t r;
    asm("cvt.rna.tf32.f32 %0, %1;" : "=r"(r) : "f"(f));
    return r;
}

__device__ __forceinline__ void mma_tf32(float c[4], const uint32_t a[4],
                                         uint32_t b0, uint32_t b1) {
    asm volatile(
        "mma.sync.aligned.m16n8k8.row.col.f32.tf32.tf32.f32 "
        "{%0,%1,%2,%3}, {%4,%5,%6,%7}, {%8,%9}, {%0,%1,%2,%3};"
        : "+f"(c[0]), "+f"(c[1]), "+f"(c[2]), "+f"(c[3])
        : "r"(a[0]), "r"(a[1]), "r"(a[2]), "r"(a[3]), "r"(b0), "r"(b1));
}

// Smem layout (30,592 B): s_p overlays s_q (s_q dead after A-fragment build).
//   [0,     15360)  s_q fp32 [64][36] (9216 B)  ||  s_p tf32 [4 warps][16][60] (15360 B)
//                   P row stride 60: covers key cols 0..55, and 60g mod 32 = 28g
//                   puts all 8 g-values in distinct banks (bank-conflict-free frag reads).
//   [15360, 23424)  s_k tf32 [56][36]  keys, d permuted: pd = (d&3)*8 + (d>>3)*2 + ((d>>2)&1)
//   [23424, 30592)  s_v tf32 [32][56]  transposed, key permuted: pk = (k>>3)*8 + (k&3)*2 + ((k>>2)&1)
#define PSTRIDE 60
#define OFF_K 15360
#define OFF_V 23424
#define VSTRIDE 56
#define SMEM_BYTES 30592

__global__ void __launch_bounds__(128)
window_attn_mma2(const float* __restrict__ qkv, float* __restrict__ out) {
    __shared__ __align__(16) unsigned char smem_raw[SMEM_BYTES];
    float*    s_q = (float*)smem_raw;
    uint32_t* s_p = (uint32_t*)smem_raw;
    uint32_t* s_k = (uint32_t*)(smem_raw + OFF_K);
    uint32_t* s_v = (uint32_t*)(smem_raw + OFF_V);

    const int bh = blockIdx.x;
    const int b  = bh >> 3;
    const int h  = bh & 7;
    const int w  = b & (NWIN - 1);
    const float* base = qkv + (size_t)b * MT * 768;
    const int tid = threadIdx.x;

    // ---- zero K/V region (padded keys 50..55 / unused cols must be 0, not garbage) ----
    {
        float4 z = make_float4(0.f, 0.f, 0.f, 0.f);
        float4* zp = (float4*)(smem_raw + OFF_K);
        for (int i = tid; i < (SMEM_BYTES - OFF_K) / 16; i += 128) zp[i] = z;
    }
    // ---- stage Q (fp32, pre-scaled, rows >=49 zeroed; row r = token r+1) ----
    for (int i = tid; i < 64 * 8; i += 128) {
        int row = i >> 3, c = i & 7;
        float4 v = make_float4(0.f, 0.f, 0.f, 0.f);
        if (row < NQ) {
            v = *(const float4*)(base + (row + 1) * 768 + h * 32 + c * 4);
            v.x *= SCALE; v.y *= SCALE; v.z *= SCALE; v.w *= SCALE;
        }
        *(float4*)&s_q[row * 36 + c * 4] = v;
    }
    __syncthreads();  // zero-fill complete before permuted K/V stores
    // ---- stage K (tf32, permuted d) and V (tf32, transposed + permuted key) ----
    for (int i = tid; i < MT * 8; i += 128) {
        int tok = i >> 3, c = i & 7;
        const float* row = base + tok * 768 + h * 32 + c * 4;
        float4 kv = *(const float4*)(row + 256);
        float4 vv = *(const float4*)(row + 512);
        int pdb = (c >> 1) * 2 + (c & 1);     // pd for d = 4c+e is e*8 + pdb
        uint32_t* kr = s_k + tok * 36 + pdb;
        kr[0] = f2tf(kv.x); kr[8] = f2tf(kv.y); kr[16] = f2tf(kv.z); kr[24] = f2tf(kv.w);
        int pk = (tok >> 3) * 8 + (tok & 3) * 2 + ((tok >> 2) & 1);
        s_v[(4 * c + 0) * VSTRIDE + pk] = f2tf(vv.x);
        s_v[(4 * c + 1) * VSTRIDE + pk] = f2tf(vv.y);
        s_v[(4 * c + 2) * VSTRIDE + pk] = f2tf(vv.z);
        s_v[(4 * c + 3) * VSTRIDE + pk] = f2tf(vv.w);
    }
    __syncthreads();

    const int warp = tid >> 5, lane = tid & 31;
    const int g = lane >> 2, t = lane & 3;
    const int qrow = warp * 16 + g;

    // ---- A fragments (Q) with hi/lo compensation, built once in registers ----
    uint32_t ahi[4][4], alo[4][4];
    #pragma unroll
    for (int kc = 0; kc < 4; kc++) {
        float f0 = s_q[qrow * 36 + t + 8 * kc];
        float f1 = s_q[(qrow + 8) * 36 + t + 8 * kc];
        float f2 = s_q[qrow * 36 + t + 4 + 8 * kc];
        float f3 = s_q[(qrow + 8) * 36 + t + 4 + 8 * kc];
        ahi[kc][0] = f2tf(f0); alo[kc][0] = f2tf(f0 - __uint_as_float(ahi[kc][0]));
        ahi[kc][1] = f2tf(f1); alo[kc][1] = f2tf(f1 - __uint_as_float(ahi[kc][1]));
        ahi[kc][2] = f2tf(f2); alo[kc][2] = f2tf(f2 - __uint_as_float(ahi[kc][2]));
        ahi[kc][3] = f2tf(f3); alo[kc][3] = f2tf(f3 - __uint_as_float(ahi[kc][3]));
    }
    __syncthreads();  // s_q dead everywhere -> s_p region reusable

    // ---- QK^T: per nt, 2 x uint4 LDS give B-frags for all 4 k-chunks ----
    float c[7][4];
    #pragma unroll
    for (int nt = 0; nt < 7; nt++)
        c[nt][0] = c[nt][1] = c[nt][2] = c[nt][3] = 0.f;

    #pragma unroll
    for (int nt = 0; nt < 7; nt++) {
        const uint32_t* kr = s_k + (8 * nt + g) * 36 + t * 8;
        uint4 B0 = *(const uint4*)kr;
        uint4 B1 = *(const uint4*)(kr + 4);
        mma_tf32(c[nt], ahi[0], B0.x, B0.y);
        mma_tf32(c[nt], alo[0], B0.x, B0.y);
        mma_tf32(c[nt], ahi[1], B0.z, B0.w);
        mma_tf32(c[nt], alo[1], B0.z, B0.w);
        mma_tf32(c[nt], ahi[2], B1.x, B1.y);
        mma_tf32(c[nt], alo[2], B1.x, B1.y);
        mma_tf32(c[nt], ahi[3], B1.z, B1.w);
        mma_tf32(c[nt], alo[3], B1.z, B1.w);
    }

    // ---- bias+mask add, exp (no max pass: logits bounded), row sums ----
    const int qa = (qrow < NQ) ? qrow : (NQ - 1);
    const int qb = (qrow + 8 < NQ) ? (qrow + 8) : (NQ - 1);
    const float* bmA = g_bm + ((size_t)(w * HN + h) * NQ + qa) * MT;
    const float* bmB = g_bm + ((size_t)(w * HN + h) * NQ + qb) * MT;

    float sum0 = 0.f, sum1 = 0.f;
    #pragma unroll
    for (int nt = 0; nt < 7; nt++) {
        int col = 8 * nt + 2 * t;
        if (col <= MT - 2) {
            float2 mA = *(const float2*)(bmA + col);
            float2 mB = *(const float2*)(bmB + col);
            c[nt][0] += mA.x; c[nt][1] += mA.y;
            c[nt][2] += mB.x; c[nt][3] += mB.y;
        } else {
            c[nt][0] = c[nt][1] = c[nt][2] = c[nt][3] = -1e30f;
        }
        c[nt][0] = __expf(c[nt][0]);
        c[nt][1] = __expf(c[nt][1]);
        c[nt][2] = __expf(c[nt][2]);
        c[nt][3] = __expf(c[nt][3]);
        sum0 += c[nt][0] + c[nt][1];
        sum1 += c[nt][2] + c[nt][3];
    }
    sum0 += __shfl_xor_sync(0xffffffffu, sum0, 1);
    sum0 += __shfl_xor_sync(0xffffffffu, sum0, 2);
    sum1 += __shfl_xor_sync(0xffffffffu, sum1, 1);
    sum1 += __shfl_xor_sync(0xffffffffu, sum1, 2);
    const float inv0 = 1.0f / sum0;
    const float inv1 = 1.0f / sum1;

    // ---- normalize, convert to tf32, stage P (per-warp region, [row][key] stride 60) ----
    uint32_t* pw = s_p + warp * 16 * PSTRIDE;
    #pragma unroll
    for (int nt = 0; nt < 7; nt++) {
        int col = 8 * nt + 2 * t;
        uint2 pA, pB;
        pA.x = f2tf(c[nt][0] * inv0); pA.y = f2tf(c[nt][1] * inv0);
        pB.x = f2tf(c[nt][2] * inv1); pB.y = f2tf(c[nt][3] * inv1);
        *(uint2*)&pw[g * PSTRIDE + col]       = pA;
        *(uint2*)&pw[(g + 8) * PSTRIDE + col] = pB;
    }
    __syncwarp();

    // ---- PV: A from staged P (bank-clean stride 60), B from s_v (uint2, conflict-free) ----
    float o[4][4];
    #pragma unroll
    for (int nt = 0; nt < 4; nt++)
        o[nt][0] = o[nt][1] = o[nt][2] = o[nt][3] = 0.f;

    #pragma unroll
    for (int kc = 0; kc < 7; kc++) {
        uint32_t a[4];
        a[0] = pw[g * PSTRIDE + 8 * kc + t];
        a[1] = pw[(g + 8) * PSTRIDE + 8 * kc + t];
        a[2] = pw[g * PSTRIDE + 8 * kc + t + 4];
        a[3] = pw[(g + 8) * PSTRIDE + 8 * kc + t + 4];
        #pragma unroll
        for (int nt = 0; nt < 4; nt++) {
            uint2 bv = *(const uint2*)&s_v[(8 * nt + g) * VSTRIDE + kc * 8 + 2 * t];
            mma_tf32(o[nt], a, bv.x, bv.y);
        }
    }

    // ---- store ----
    if (qrow < NQ) {
        float* orow = out + ((size_t)b * NQ + qrow) * DIM + h * 32;
        #pragma unroll
        for (int nt = 0; nt < 4; nt++) {
            float2 v2; v2.x = o[nt][0]; v2.y = o[nt][1];
            *(float2*)(orow + 8 * nt + 2 * t) = v2;
        }
    }
    if (qrow + 8 < NQ) {
        float* orow = out + ((size_t)b * NQ + qrow + 8) * DIM + h * 32;
        #pragma unroll
        for (int nt = 0; nt < 4; nt++) {
            float2 v2; v2.x = o[nt][2]; v2.y = o[nt][3];
            *(float2*)(orow + 8 * nt + 2 * t) = v2;
        }
    }
}

extern "C" void kernel_launch(void* const* d_in, const int* in_sizes, int n_in,
                              void* d_out, int out_size) {
    const float* qkv        = (const float*)d_in[0];
    const float* mask       = (const float*)d_in[1];
    const float* bias_table = (const float*)d_in[2];
    const int*   rel_index  = (const int*)d_in[3];
    float* out = (float*)d_out;

    const int total = NWIN * HN * NQ * MT;
    precompute_bm_kernel<<<(total + 255) / 256, 256>>>(mask, bias_table, rel_index);
    window_attn_mma2<<<BWIN * HN, 128>>>(qkv, out);
}

// round 11
// speedup vs baseline: 3.1657x; 1.1115x over previous
#include <cuda_runtime.h>
#include <cstdint>

#define NWIN 64
#define HN 8
#define NQ 49
#define MT 50
#define BWIN 4096
#define DIM 256
#define SCALE 0.17677669529663689f

// Precombined (mask + relative position bias) table: [w][h][qi][j], ~5 MB, L2-resident.
__device__ float g_bm[NWIN * HN * NQ * MT];

__global__ void precompute_bm_kernel(const float* __restrict__ mask,
                                     const float* __restrict__ bias_table,
                                     const int* __restrict__ rel_index) {
    int i = blockIdx.x * blockDim.x + threadIdx.x;
    if (i >= NWIN * HN * NQ * MT) return;
    int j  = i % MT;
    int r  = i / MT;
    int qi = r % NQ; r /= NQ;
    int h  = r % HN;
    int w  = r / HN;
    float v = mask[(w * NQ + qi) * MT + j];
    if (j > 0) {
        int idx = rel_index[qi * NQ + (j - 1)];
        v += bias_table[idx * HN + h];
    }
    g_bm[i] = v;
}

__device__ __forceinline__ uint32_t f2tf(float f) {
    uint32_t r;
    asm("cvt.rna.tf32.f32 %0, %1;" : "=r"(r) : "f"(f));
    return r;
}

__device__ __forceinline__ void mma_tf32(float c[4], const uint32_t a[4],
                                         uint32_t b0, uint32_t b1) {
    asm volatile(
        "mma.sync.aligned.m16n8k8.row.col.f32.tf32.tf32.f32 "
        "{%0,%1,%2,%3}, {%4,%5,%6,%7}, {%8,%9}, {%0,%1,%2,%3};"
        : "+f"(c[0]), "+f"(c[1]), "+f"(c[2]), "+f"(c[3])
        : "r"(a[0]), "r"(a[1]), "r"(a[2]), "r"(a[3]), "r"(b0), "r"(b1));
}

// Smem layout (32,384 B): s_p overlays s_q (s_q dead after A-fragment build).
//   [0,     15360)  s_q fp32 [64][36] (9216 B)  ||  s_p tf32 [4 warps][16][60]
//   [15360, 23424)  s_k tf32 [56][36]  keys, d permuted: pd = (d&3)*8 + (d>>3)*2 + ((d>>2)&1)
//   [23424, 32384)  s_v tf32 [56][40]  identity [tok][d]; PV B-frag reads at banks
//                   (40(8kc+t) + 8nt + g) mod 32 = 8t + 8nt + g -> all 32 distinct, conflict-free.
#define PSTRIDE 60
#define OFF_K 15360
#define OFF_V 23424
#define VSTRIDE 40
#define SMEM_BYTES 32384

__global__ void __launch_bounds__(128)
window_attn_mma3(const float* __restrict__ qkv, float* __restrict__ out) {
    __shared__ __align__(16) unsigned char smem_raw[SMEM_BYTES];
    float*    s_q = (float*)smem_raw;
    uint32_t* s_p = (uint32_t*)smem_raw;
    uint32_t* s_k = (uint32_t*)(smem_raw + OFF_K);
    uint32_t* s_v = (uint32_t*)(smem_raw + OFF_V);

    const int bh = blockIdx.x;
    const int b  = bh >> 3;
    const int h  = bh & 7;
    const int w  = b & (NWIN - 1);
    const float* base = qkv + (size_t)b * MT * 768;
    const int tid = threadIdx.x;

    // ---- stage Q (fp32, pre-scaled, rows >=49 zeroed; row r = token r+1) ----
    for (int i = tid; i < 64 * 8; i += 128) {
        int row = i >> 3, c = i & 7;
        float4 v = make_float4(0.f, 0.f, 0.f, 0.f);
        if (row < NQ) {
            v = *(const float4*)(base + (row + 1) * 768 + h * 32 + c * 4);
            v.x *= SCALE; v.y *= SCALE; v.z *= SCALE; v.w *= SCALE;
        }
        *(float4*)&s_q[row * 36 + c * 4] = v;
    }
    // ---- stage K (tf32, permuted d) and V (tf32, identity [tok][d], vectorized) ----
    // Loop covers tok 0..55: tok 50..55 write zeros (fused pad-fill, no separate pass).
    for (int i = tid; i < 56 * 8; i += 128) {
        int tok = i >> 3, c = i & 7;
        float4 kv = make_float4(0.f, 0.f, 0.f, 0.f);
        float4 vv = kv;
        if (tok < MT) {
            const float* row = base + tok * 768 + h * 32 + c * 4;
            kv = *(const float4*)(row + 256);
            vv = *(const float4*)(row + 512);
        }
        uint32_t* kr = s_k + tok * 36 + c;   // pd for d=4c+e is e*8 + c
        kr[0] = f2tf(kv.x); kr[8] = f2tf(kv.y); kr[16] = f2tf(kv.z); kr[24] = f2tf(kv.w);
        uint4 vt;
        vt.x = f2tf(vv.x); vt.y = f2tf(vv.y); vt.z = f2tf(vv.z); vt.w = f2tf(vv.w);
        *(uint4*)&s_v[tok * VSTRIDE + 4 * c] = vt;
    }
    __syncthreads();

    const int warp = tid >> 5, lane = tid & 31;
    const int g = lane >> 2, t = lane & 3;
    const int qrow = warp * 16 + g;

    // ---- A fragments (Q) with hi/lo compensation, built once in registers ----
    uint32_t ahi[4][4], alo[4][4];
    #pragma unroll
    for (int kc = 0; kc < 4; kc++) {
        float f0 = s_q[qrow * 36 + t + 8 * kc];
        float f1 = s_q[(qrow + 8) * 36 + t + 8 * kc];
        float f2 = s_q[qrow * 36 + t + 4 + 8 * kc];
        float f3 = s_q[(qrow + 8) * 36 + t + 4 + 8 * kc];
        ahi[kc][0] = f2tf(f0); alo[kc][0] = f2tf(f0 - __uint_as_float(ahi[kc][0]));
        ahi[kc][1] = f2tf(f1); alo[kc][1] = f2tf(f1 - __uint_as_float(ahi[kc][1]));
        ahi[kc][2] = f2tf(f2); alo[kc][2] = f2tf(f2 - __uint_as_float(ahi[kc][2]));
        ahi[kc][3] = f2tf(f3); alo[kc][3] = f2tf(f3 - __uint_as_float(ahi[kc][3]));
    }
    __syncthreads();  // s_q dead everywhere -> s_p region reusable

    // ---- QK^T: per nt, 2 x uint4 LDS give B-frags for all 4 k-chunks ----
    float c[7][4];
    #pragma unroll
    for (int nt = 0; nt < 7; nt++)
        c[nt][0] = c[nt][1] = c[nt][2] = c[nt][3] = 0.f;

    #pragma unroll
    for (int nt = 0; nt < 7; nt++) {
        const uint32_t* kr = s_k + (8 * nt + g) * 36 + t * 8;
        uint4 B0 = *(const uint4*)kr;
        uint4 B1 = *(const uint4*)(kr + 4);
        mma_tf32(c[nt], ahi[0], B0.x, B0.y);
        mma_tf32(c[nt], alo[0], B0.x, B0.y);
        mma_tf32(c[nt], ahi[1], B0.z, B0.w);
        mma_tf32(c[nt], alo[1], B0.z, B0.w);
        mma_tf32(c[nt], ahi[2], B1.x, B1.y);
        mma_tf32(c[nt], alo[2], B1.x, B1.y);
        mma_tf32(c[nt], ahi[3], B1.z, B1.w);
        mma_tf32(c[nt], alo[3], B1.z, B1.w);
    }

    // ---- bias+mask add, exp (no max pass: logits bounded), row sums ----
    const int qa = (qrow < NQ) ? qrow : (NQ - 1);
    const int qb = (qrow + 8 < NQ) ? (qrow + 8) : (NQ - 1);
    const float* bmA = g_bm + ((size_t)(w * HN + h) * NQ + qa) * MT;
    const float* bmB = g_bm + ((size_t)(w * HN + h) * NQ + qb) * MT;

    float sum0 = 0.f, sum1 = 0.f;
    #pragma unroll
    for (int nt = 0; nt < 7; nt++) {
        int col = 8 * nt + 2 * t;
        if (col <= MT - 2) {
            float2 mA = *(const float2*)(bmA + col);
            float2 mB = *(const float2*)(bmB + col);
            c[nt][0] += mA.x; c[nt][1] += mA.y;
            c[nt][2] += mB.x; c[nt][3] += mB.y;
        } else {
            c[nt][0] = c[nt][1] = c[nt][2] = c[nt][3] = -1e30f;
        }
        c[nt][0] = __expf(c[nt][0]);
        c[nt][1] = __expf(c[nt][1]);
        c[nt][2] = __expf(c[nt][2]);
        c[nt][3] = __expf(c[nt][3]);
        sum0 += c[nt][0] + c[nt][1];
        sum1 += c[nt][2] + c[nt][3];
    }
    sum0 += __shfl_xor_sync(0xffffffffu, sum0, 1);
    sum0 += __shfl_xor_sync(0xffffffffu, sum0, 2);
    sum1 += __shfl_xor_sync(0xffffffffu, sum1, 1);
    sum1 += __shfl_xor_sync(0xffffffffu, sum1, 2);
    const float inv0 = 1.0f / sum0;
    const float inv1 = 1.0f / sum1;

    // ---- normalize, convert to tf32, stage P (per-warp region, [row][key] stride 60) ----
    uint32_t* pw = s_p + warp * 16 * PSTRIDE;
    #pragma unroll
    for (int nt = 0; nt < 7; nt++) {
        int col = 8 * nt + 2 * t;
        uint2 pA, pB;
        pA.x = f2tf(c[nt][0] * inv0); pA.y = f2tf(c[nt][1] * inv0);
        pB.x = f2tf(c[nt][2] * inv1); pB.y = f2tf(c[nt][3] * inv1);
        *(uint2*)&pw[g * PSTRIDE + col]       = pA;
        *(uint2*)&pw[(g + 8) * PSTRIDE + col] = pB;
    }
    __syncwarp();

    // ---- PV: A from staged P (bank-clean stride 60), B from s_v (scalar, conflict-free) ----
    float o[4][4];
    #pragma unroll
    for (int nt = 0; nt < 4; nt++)
        o[nt][0] = o[nt][1] = o[nt][2] = o[nt][3] = 0.f;

    #pragma unroll
    for (int kc = 0; kc < 7; kc++) {
        uint32_t a[4];
        a[0] = pw[g * PSTRIDE + 8 * kc + t];
        a[1] = pw[(g + 8) * PSTRIDE + 8 * kc + t];
        a[2] = pw[g * PSTRIDE + 8 * kc + t + 4];
        a[3] = pw[(g + 8) * PSTRIDE + 8 * kc + t + 4];
        const uint32_t* v0 = s_v + (8 * kc + t) * VSTRIDE + g;
        const uint32_t* v1 = s_v + (8 * kc + t + 4) * VSTRIDE + g;
        #pragma unroll
        for (int nt = 0; nt < 4; nt++) {
            mma_tf32(o[nt], a, v0[8 * nt], v1[8 * nt]);
        }
    }

    // ---- store ----
    if (qrow < NQ) {
        float* orow = out + ((size_t)b * NQ + qrow) * DIM + h * 32;
        #pragma unroll
        for (int nt = 0; nt < 4; nt++) {
            float2 v2; v2.x = o[nt][0]; v2.y = o[nt][1];
            *(float2*)(orow + 8 * nt + 2 * t) = v2;
        }
    }
    if (qrow + 8 < NQ) {
        float* orow = out + ((size_t)b * NQ + qrow + 8) * DIM + h * 32;
        #pragma unroll
        for (int nt = 0; nt < 4; nt++) {
            float2 v2; v2.x = o[nt][2]; v2.y = o[nt][3];
            *(float2*)(orow + 8 * nt + 2 * t) = v2;
        }
    }
}

extern "C" void kernel_launch(void* const* d_in, const int* in_sizes, int n_in,
                              void* d_out, int out_size) {
    const float* qkv        = (const float*)d_in[0];
    const float* mask       = (const float*)d_in[1];
    const float* bias_table = (const float*)d_in[2];
    const int*   rel_index  = (const int*)d_in[3];
    float* out = (float*)d_out;

    const int total = NWIN * HN * NQ * MT;
    precompute_bm_kernel<<<(total + 255) / 256, 256>>>(mask, bias_table, rel_index);
    window_attn_mma3<<<BWIN * HN, 128>>>(qkv, out);
}

// round 13
// speedup vs baseline: 3.2237x; 1.0183x over previous
#include <cuda_runtime.h>
#include <cstdint>

#define NWIN 64
#define HN 8
#define NQ 49
#define MT 50
#define BWIN 4096
#define DIM 256
#define SCALE 0.17677669529663689f

// Bias+mask table pre-laid-out in C-fragment order:
//   [w][h][warp 4][nt 7][half 2][lane 32][e 2]  (7.34 MB, L2-resident)
// half=0 -> c0,c1 (row = 16*warp + g), half=1 -> c2,c3 (row +8); col = 8*nt + 2*t + e.
// Padding baked in: col>=50 -> -1e30 (exp -> 0), row>=49 -> 0.
#define BM3_TOTAL (NWIN * HN * 4 * 7 * 2 * 32 * 2)
__device__ float g_bm3[BM3_TOTAL];

__global__ void precompute_bm3(const float* __restrict__ mask,
                               const float* __restrict__ bias_table,
                               const int* __restrict__ rel_index) {
    int i = blockIdx.x * blockDim.x + threadIdx.x;
    if (i >= BM3_TOTAL) return;
    int e    = i & 1;
    int lane = (i >> 1) & 31;
    int half = (i >> 6) & 1;
    int nt   = (i >> 7) % 7;
    int rest = i / (7 << 7);          // 7*128 elements per (w,h,warp) per nt-set
    int warp = rest & 3;
    int h    = (rest >> 2) & 7;
    int w    = rest >> 5;
    int row = warp * 16 + (lane >> 2) + half * 8;
    int col = nt * 8 + (lane & 3) * 2 + e;
    float v;
    if (col >= MT) v = -1e30f;
    else if (row >= NQ) v = 0.f;
    else {
        v = mask[(w * NQ + row) * MT + col];
        if (col > 0) v += bias_table[rel_index[row * NQ + (col - 1)] * HN + h];
    }
    g_bm3[i] = v;
}

__device__ __forceinline__ uint32_t f2tf(float f) {
    uint32_t r;
    asm("cvt.rna.tf32.f32 %0, %1;" : "=r"(r) : "f"(f));
    return r;
}

__device__ __forceinline__ void mma_tf32(float c[4], const uint32_t a[4],
                                         uint32_t b0, uint32_t b1) {
    asm volatile(
        "mma.sync.aligned.m16n8k8.row.col.f32.tf32.tf32.f32 "
        "{%0,%1,%2,%3}, {%4,%5,%6,%7}, {%8,%9}, {%0,%1,%2,%3};"
        : "+f"(c[0]), "+f"(c[1]), "+f"(c[2]), "+f"(c[3])
        : "r"(a[0]), "r"(a[1]), "r"(a[2]), "r"(a[3]), "r"(b0), "r"(b1));
}

// Smem layout (32,384 B): s_p overlays s_q (s_q dead after A-fragment build).
//   [0,     15360)  s_q fp32 [64][36] (9216 B)  ||  s_p tf32 [4 warps][16][60]
//   [15360, 23424)  s_k tf32 [56][36]  keys, d permuted: pd = (d&3)*8 + (d>>3)*2 + ((d>>2)&1)
//   [23424, 32384)  s_v tf32 [56][40]  identity [tok][d]; PV B-frag reads conflict-free.
#define PSTRIDE 60
#define OFF_K 15360
#define OFF_V 23424
#define VSTRIDE 40
#define SMEM_BYTES 32384

__global__ void __launch_bounds__(128)
window_attn_mma4(const float* __restrict__ qkv, float* __restrict__ out) {
    __shared__ __align__(16) unsigned char smem_raw[SMEM_BYTES];
    float*    s_q = (float*)smem_raw;
    uint32_t* s_p = (uint32_t*)smem_raw;
    uint32_t* s_k = (uint32_t*)(smem_raw + OFF_K);
    uint32_t* s_v = (uint32_t*)(smem_raw + OFF_V);

    const int bh = blockIdx.x;
    const int b  = bh >> 3;
    const int h  = bh & 7;
    const int w  = b & (NWIN - 1);
    const float* base = qkv + (size_t)b * MT * 768;
    const int tid = threadIdx.x;

    // ---- stage Q (fp32, pre-scaled, rows >=49 zeroed; row r = token r+1) ----
    for (int i = tid; i < 64 * 8; i += 128) {
        int row = i >> 3, c = i & 7;
        float4 v = make_float4(0.f, 0.f, 0.f, 0.f);
        if (row < NQ) {
            v = *(const float4*)(base + (row + 1) * 768 + h * 32 + c * 4);
            v.x *= SCALE; v.y *= SCALE; v.z *= SCALE; v.w *= SCALE;
        }
        *(float4*)&s_q[row * 36 + c * 4] = v;
    }
    // ---- stage K (tf32, permuted d) and V (tf32, identity [tok][d], vectorized) ----
    // Loop covers tok 0..55: tok 50..55 write zeros (fused pad-fill).
    for (int i = tid; i < 56 * 8; i += 128) {
        int tok = i >> 3, c = i & 7;
        float4 kv = make_float4(0.f, 0.f, 0.f, 0.f);
        float4 vv = kv;
        if (tok < MT) {
            const float* row = base + tok * 768 + h * 32 + c * 4;
            kv = *(const float4*)(row + 256);
            vv = *(const float4*)(row + 512);
        }
        uint32_t* kr = s_k + tok * 36 + c;   // pd for d=4c+e is e*8 + c
        kr[0] = f2tf(kv.x); kr[8] = f2tf(kv.y); kr[16] = f2tf(kv.z); kr[24] = f2tf(kv.w);
        uint4 vt;
        vt.x = f2tf(vv.x); vt.y = f2tf(vv.y); vt.z = f2tf(vv.z); vt.w = f2tf(vv.w);
        *(uint4*)&s_v[tok * VSTRIDE + 4 * c] = vt;
    }
    __syncthreads();

    const int warp = tid >> 5, lane = tid & 31;
    const int g = lane >> 2, t = lane & 3;
    const int qrow = warp * 16 + g;

    // ---- A fragments (Q) with hi/lo compensation, built once in registers ----
    uint32_t ahi[4][4], alo[4][4];
    #pragma unroll
    for (int kc = 0; kc < 4; kc++) {
        float f0 = s_q[qrow * 36 + t + 8 * kc];
        float f1 = s_q[(qrow + 8) * 36 + t + 8 * kc];
        float f2 = s_q[qrow * 36 + t + 4 + 8 * kc];
        float f3 = s_q[(qrow + 8) * 36 + t + 4 + 8 * kc];
        ahi[kc][0] = f2tf(f0); alo[kc][0] = f2tf(f0 - __uint_as_float(ahi[kc][0]));
        ahi[kc][1] = f2tf(f1); alo[kc][1] = f2tf(f1 - __uint_as_float(ahi[kc][1]));
        ahi[kc][2] = f2tf(f2); alo[kc][2] = f2tf(f2 - __uint_as_float(ahi[kc][2]));
        ahi[kc][3] = f2tf(f3); alo[kc][3] = f2tf(f3 - __uint_as_float(ahi[kc][3]));
    }
    __syncthreads();  // s_q dead everywhere -> s_p region reusable

    // ---- QK^T: per nt, 2 x uint4 LDS give B-frags for all 4 k-chunks ----
    float c[7][4];
    #pragma unroll
    for (int nt = 0; nt < 7; nt++)
        c[nt][0] = c[nt][1] = c[nt][2] = c[nt][3] = 0.f;

    #pragma unroll
    for (int nt = 0; nt < 7; nt++) {
        const uint32_t* kr = s_k + (8 * nt + g) * 36 + t * 8;
        uint4 B0 = *(const uint4*)kr;
        uint4 B1 = *(const uint4*)(kr + 4);
        mma_tf32(c[nt], ahi[0], B0.x, B0.y);
        mma_tf32(c[nt], alo[0], B0.x, B0.y);
        mma_tf32(c[nt], ahi[1], B0.z, B0.w);
        mma_tf32(c[nt], alo[1], B0.z, B0.w);
        mma_tf32(c[nt], ahi[2], B1.x, B1.y);
        mma_tf32(c[nt], alo[2], B1.x, B1.y);
        mma_tf32(c[nt], ahi[3], B1.z, B1.w);
        mma_tf32(c[nt], alo[3], B1.z, B1.w);
    }

    // ---- bias+mask add (fragment-layout table, coalesced LDG.64), exp, row sums ----
    const float2* bmw = (const float2*)g_bm3 +
                        (size_t)(((w * HN + h) * 4 + warp) * 448) + lane;
    float sum0 = 0.f, sum1 = 0.f;
    #pragma unroll
    for (int nt = 0; nt < 7; nt++) {
        float2 mA = bmw[nt * 64];        // half 0: rows g
        float2 mB = bmw[nt * 64 + 32];   // half 1: rows g+8
        c[nt][0] = __expf(c[nt][0] + mA.x);
        c[nt][1] = __expf(c[nt][1] + mA.y);
        c[nt][2] = __expf(c[nt][2] + mB.x);
        c[nt][3] = __expf(c[nt][3] + mB.y);
        sum0 += c[nt][0] + c[nt][1];
        sum1 += c[nt][2] + c[nt][3];
    }
    sum0 += __shfl_xor_sync(0xffffffffu, sum0, 1);
    sum0 += __shfl_xor_sync(0xffffffffu, sum0, 2);
    sum1 += __shfl_xor_sync(0xffffffffu, sum1, 1);
    sum1 += __shfl_xor_sync(0xffffffffu, sum1, 2);
    const float inv0 = 1.0f / sum0;
    const float inv1 = 1.0f / sum1;

    // ---- stage UNNORMALIZED P (tf32) -- normalization folded into output store ----
    uint32_t* pw = s_p + warp * 16 * PSTRIDE;
    #pragma unroll
    for (int nt = 0; nt < 7; nt++) {
        int col = 8 * nt + 2 * t;
        uint2 pA, pB;
        pA.x = f2tf(c[nt][0]); pA.y = f2tf(c[nt][1]);
        pB.x = f2tf(c[nt][2]); pB.y = f2tf(c[nt][3]);
        *(uint2*)&pw[g * PSTRIDE + col]       = pA;
        *(uint2*)&pw[(g + 8) * PSTRIDE + col] = pB;
    }
    __syncwarp();

    // ---- PV: A from staged P (bank-clean stride 60), B from s_v (scalar, conflict-free) ----
    float o[4][4];
    #pragma unroll
    for (int nt = 0; nt < 4; nt++)
        o[nt][0] = o[nt][1] = o[nt][2] = o[nt][3] = 0.f;

    #pragma unroll
    for (int kc = 0; kc < 7; kc++) {
        uint32_t a[4];
        a[0] = pw[g * PSTRIDE + 8 * kc + t];
        a[1] = pw[(g + 8) * PSTRIDE + 8 * kc + t];
        a[2] = pw[g * PSTRIDE + 8 * kc + t + 4];
        a[3] = pw[(g + 8) * PSTRIDE + 8 * kc + t + 4];
        const uint32_t* v0 = s_v + (8 * kc + t) * VSTRIDE + g;
        const uint32_t* v1 = s_v + (8 * kc + t + 4) * VSTRIDE + g;
        #pragma unroll
        for (int nt = 0; nt < 4; nt++) {
            mma_tf32(o[nt], a, v0[8 * nt], v1[8 * nt]);
        }
    }

    // ---- store (normalize here) ----
    if (qrow < NQ) {
        float* orow = out + ((size_t)b * NQ + qrow) * DIM + h * 32;
        #pragma unroll
        for (int nt = 0; nt < 4; nt++) {
            float2 v2; v2.x = o[nt][0] * inv0; v2.y = o[nt][1] * inv0;
            *(float2*)(orow + 8 * nt + 2 * t) = v2;
        }
    }
    if (qrow + 8 < NQ) {
        float* orow = out + ((size_t)b * NQ + qrow + 8) * DIM + h * 32;
        #pragma unroll
        for (int nt = 0; nt < 4; nt++) {
            float2 v2; v2.x = o[nt][2] * inv1; v2.y = o[nt][3] * inv1;
            *(float2*)(orow + 8 * nt + 2 * t) = v2;
        }
    }
}

extern "C" void kernel_launch(void* const* d_in, const int* in_sizes, int n_in,
                              void* d_out, int out_size) {
    const float* qkv        = (const float*)d_in[0];
    const float* mask       = (const float*)d_in[1];
    const float* bias_table = (const float*)d_in[2];
    const int*   rel_index  = (const int*)d_in[3];
    float* out = (float*)d_out;

    precompute_bm3<<<(BM3_TOTAL + 255) / 256, 256>>>(mask, bias_table, rel_index);
    window_attn_mma4<<<BWIN * HN, 128>>>(qkv, out);
}

// round 14
// speedup vs baseline: 4.0832x; 1.2666x over previous
#include <cuda_runtime.h>
#include <cuda_fp16.h>
#include <cstdint>

#define NWIN 64
#define HN 8
#define NQ 49
#define MT 50
#define BWIN 4096
#define DIM 256
#define SCALE 0.17677669529663689f

// Bias+mask table in C-fragment order: [w][h][warp 4][nt 7][half 2][lane 32][e 2]
// col>=50 -> -1e30, row>=49 -> 0.  (7.34 MB, L2-resident; verified in R13)
#define BM3_TOTAL (NWIN * HN * 4 * 7 * 2 * 32 * 2)
__device__ float g_bm3[BM3_TOTAL];

__global__ void precompute_bm3(const float* __restrict__ mask,
                               const float* __restrict__ bias_table,
                               const int* __restrict__ rel_index) {
    int i = blockIdx.x * blockDim.x + threadIdx.x;
    if (i >= BM3_TOTAL) return;
    int e    = i & 1;
    int lane = (i >> 1) & 31;
    int half = (i >> 6) & 1;
    int nt   = (i >> 7) % 7;
    int rest = i / (7 << 7);
    int warp = rest & 3;
    int h    = (rest >> 2) & 7;
    int w    = rest >> 5;
    int row = warp * 16 + (lane >> 2) + half * 8;
    int col = nt * 8 + (lane & 3) * 2 + e;
    float v;
    if (col >= MT) v = -1e30f;
    else if (row >= NQ) v = 0.f;
    else {
        v = mask[(w * NQ + row) * MT + col];
        if (col > 0) v += bias_table[rel_index[row * NQ + (col - 1)] * HN + h];
    }
    g_bm3[i] = v;
}

// pack two fp32 into half2 (a -> low, b -> high), rna
__device__ __forceinline__ uint32_t f2h2(float a, float b) {
    uint32_t r;
    asm("cvt.rn.f16x2.f32 %0, %1, %2;" : "=r"(r) : "f"(b), "f"(a));
    return r;
}

__device__ __forceinline__ void mma_f16(float c[4], const uint32_t a[4],
                                        uint32_t b0, uint32_t b1) {
    asm volatile(
        "mma.sync.aligned.m16n8k16.row.col.f32.f16.f16.f32 "
        "{%0,%1,%2,%3}, {%4,%5,%6,%7}, {%8,%9}, {%0,%1,%2,%3};"
        : "+f"(c[0]), "+f"(c[1]), "+f"(c[2]), "+f"(c[3])
        : "r"(a[0]), "r"(a[1]), "r"(a[2]), "r"(a[3]), "r"(b0), "r"(b1));
}

// Smem (18,304 B), all fragment strides ≡ 4 (mod 32) words -> bank 4g+t, conflict-free:
//   [0,     9216)  s_q fp32 [64][36]  ||  s_p half2 [4 warps][16 rows][36 words]
//   [9216, 13696)  s_kh half2 [56 keys][20 words]  {K[key][2dp], K[key][2dp+1]}
//   [13696,18304)  s_vt half2 [32 d][36 words]     {V[2kp][d],  V[2kp+1][d]}
#define OFF_K 9216
#define OFF_V 13696
#define KSTR 20
#define VSTR 36
#define PSTR 36
#define SMEM_BYTES 18304

__global__ void __launch_bounds__(128)
window_attn_h16(const float* __restrict__ qkv, float* __restrict__ out) {
    __shared__ __align__(16) unsigned char smem_raw[SMEM_BYTES];
    float*    s_q  = (float*)smem_raw;
    uint32_t* s_p  = (uint32_t*)smem_raw;
    uint32_t* s_kh = (uint32_t*)(smem_raw + OFF_K);
    uint32_t* s_vt = (uint32_t*)(smem_raw + OFF_V);

    const int bh = blockIdx.x;
    const int b  = bh >> 3;
    const int h  = bh & 7;
    const int w  = b & (NWIN - 1);
    const float* base = qkv + (size_t)b * MT * 768;
    const int tid = threadIdx.x;

    // ---- stage Q (fp32, pre-scaled, rows >=49 zeroed; row r = token r+1) ----
    for (int i = tid; i < 64 * 8; i += 128) {
        int row = i >> 3, c = i & 7;
        float4 v = make_float4(0.f, 0.f, 0.f, 0.f);
        if (row < NQ) {
            v = *(const float4*)(base + (row + 1) * 768 + h * 32 + c * 4);
            v.x *= SCALE; v.y *= SCALE; v.z *= SCALE; v.w *= SCALE;
        }
        *(float4*)&s_q[row * 36 + c * 4] = v;
    }
    // ---- stage K as half2 pairs along d: s_kh[tok][dp] (toks 50..55 zeroed) ----
    for (int i = tid; i < 56 * 8; i += 128) {
        int tok = i >> 3, c = i & 7;
        float4 kv = make_float4(0.f, 0.f, 0.f, 0.f);
        if (tok < MT)
            kv = *(const float4*)(base + tok * 768 + 256 + h * 32 + c * 4);
        uint2 p; p.x = f2h2(kv.x, kv.y); p.y = f2h2(kv.z, kv.w);
        *(uint2*)&s_kh[tok * KSTR + 2 * c] = p;
    }
    // ---- stage V transposed as half2 pairs along key: s_vt[d][kp] (kp 28..31 zeroed) ----
    for (int i = tid; i < 32 * 8; i += 128) {
        int m = i >> 3, c = i & 7;           // m = key pair index (keys 2m, 2m+1)
        float4 v0 = make_float4(0.f, 0.f, 0.f, 0.f), v1 = v0;
        if (2 * m < MT)
            v0 = *(const float4*)(base + (2 * m) * 768 + 512 + h * 32 + c * 4);
        if (2 * m + 1 < MT)
            v1 = *(const float4*)(base + (2 * m + 1) * 768 + 512 + h * 32 + c * 4);
        s_vt[(4 * c + 0) * VSTR + m] = f2h2(v0.x, v1.x);
        s_vt[(4 * c + 1) * VSTR + m] = f2h2(v0.y, v1.y);
        s_vt[(4 * c + 2) * VSTR + m] = f2h2(v0.z, v1.z);
        s_vt[(4 * c + 3) * VSTR + m] = f2h2(v0.w, v1.w);
    }
    __syncthreads();

    const int warp = tid >> 5, lane = tid & 31;
    const int g = lane >> 2, t = lane & 3;
    const int qrow = warp * 16 + g;

    // ---- Q A-fragments (fp16 hi/lo compensation), built once ----
    // kc chunk covers d = 16kc..16kc+15; a0:[g][2t,2t+1] a1:[g+8][..] a2:[g][2t+8,2t+9] a3:[g+8][..]
    uint32_t qhi[2][4], qlo[2][4];
    #pragma unroll
    for (int kc = 0; kc < 2; kc++) {
        #pragma unroll
        for (int r = 0; r < 4; r++) {
            int row = (r & 1) ? (qrow + 8) : qrow;
            int d0  = 16 * kc + 2 * t + ((r >> 1) ? 8 : 0);
            float2 f = *(const float2*)&s_q[row * 36 + d0];
            __half2 H = __floats2half2_rn(f.x, f.y);
            float2 Hf = __half22float2(H);
            qhi[kc][r] = *(uint32_t*)&H;
            qlo[kc][r] = f2h2(f.x - Hf.x, f.y - Hf.y);
        }
    }
    __syncthreads();  // s_q dead -> s_p region reusable

    // ---- QK^T: 7 nt x 2 kc x (hi + lo) fp16 MMAs ----
    float c[7][4];
    #pragma unroll
    for (int nt = 0; nt < 7; nt++)
        c[nt][0] = c[nt][1] = c[nt][2] = c[nt][3] = 0.f;

    #pragma unroll
    for (int nt = 0; nt < 7; nt++) {
        const uint32_t* kr = s_kh + (8 * nt + g) * KSTR + t;
        #pragma unroll
        for (int kc = 0; kc < 2; kc++) {
            uint32_t b0 = kr[8 * kc];       // dp = 8kc + t
            uint32_t b1 = kr[8 * kc + 4];   // dp = 8kc + t + 4
            mma_f16(c[nt], qhi[kc], b0, b1);
            mma_f16(c[nt], qlo[kc], b0, b1);
        }
    }

    // ---- bias+mask add (coalesced frag-layout LDG), row max, exp, sums ----
    const float2* bmw = (const float2*)g_bm3 +
                        (size_t)(((w * HN + h) * 4 + warp) * 448) + lane;
    float m0 = -1e30f, m1 = -1e30f;
    #pragma unroll
    for (int nt = 0; nt < 7; nt++) {
        float2 mA = bmw[nt * 64];
        float2 mB = bmw[nt * 64 + 32];
        c[nt][0] += mA.x; c[nt][1] += mA.y;
        c[nt][2] += mB.x; c[nt][3] += mB.y;
        m0 = fmaxf(m0, fmaxf(c[nt][0], c[nt][1]));
        m1 = fmaxf(m1, fmaxf(c[nt][2], c[nt][3]));
    }
    m0 = fmaxf(m0, __shfl_xor_sync(0xffffffffu, m0, 1));
    m0 = fmaxf(m0, __shfl_xor_sync(0xffffffffu, m0, 2));
    m1 = fmaxf(m1, __shfl_xor_sync(0xffffffffu, m1, 1));
    m1 = fmaxf(m1, __shfl_xor_sync(0xffffffffu, m1, 2));

    float sum0 = 0.f, sum1 = 0.f;
    #pragma unroll
    for (int nt = 0; nt < 7; nt++) {
        c[nt][0] = __expf(c[nt][0] - m0);
        c[nt][1] = __expf(c[nt][1] - m0);
        c[nt][2] = __expf(c[nt][2] - m1);
        c[nt][3] = __expf(c[nt][3] - m1);
        sum0 += c[nt][0] + c[nt][1];
        sum1 += c[nt][2] + c[nt][3];
    }
    sum0 += __shfl_xor_sync(0xffffffffu, sum0, 1);
    sum0 += __shfl_xor_sync(0xffffffffu, sum0, 2);
    sum1 += __shfl_xor_sync(0xffffffffu, sum1, 1);
    sum1 += __shfl_xor_sync(0xffffffffu, sum1, 2);
    const float inv0 = 1.0f / sum0;
    const float inv1 = 1.0f / sum1;

    // ---- stage unnormalized P as half2 (in [0,1], safe); zero kp 28..31 ----
    uint32_t* pw = s_p + warp * 16 * PSTR;
    #pragma unroll
    for (int nt = 0; nt < 7; nt++) {
        pw[g * PSTR + 4 * nt + t]       = f2h2(c[nt][0], c[nt][1]);
        pw[(g + 8) * PSTR + 4 * nt + t] = f2h2(c[nt][2], c[nt][3]);
    }
    pw[g * PSTR + 28 + t] = 0u;
    pw[(g + 8) * PSTR + 28 + t] = 0u;
    __syncwarp();

    // ---- PV: fp16 m16n8k16, 4 kc x 4 nt; all LDS conflict-free ----
    float o[4][4];
    #pragma unroll
    for (int nt = 0; nt < 4; nt++)
        o[nt][0] = o[nt][1] = o[nt][2] = o[nt][3] = 0.f;

    #pragma unroll
    for (int kc = 0; kc < 4; kc++) {
        uint32_t a[4];
        a[0] = pw[g * PSTR + 8 * kc + t];
        a[1] = pw[(g + 8) * PSTR + 8 * kc + t];
        a[2] = pw[g * PSTR + 8 * kc + t + 4];
        a[3] = pw[(g + 8) * PSTR + 8 * kc + t + 4];
        #pragma unroll
        for (int nt = 0; nt < 4; nt++) {
            const uint32_t* vr = s_vt + (8 * nt + g) * VSTR + 8 * kc + t;
            mma_f16(o[nt], a, vr[0], vr[4]);
        }
    }

    // ---- store (normalize here) ----
    if (qrow < NQ) {
        float* orow = out + ((size_t)b * NQ + qrow) * DIM + h * 32;
        #pragma unroll
        for (int nt = 0; nt < 4; nt++) {
            float2 v2; v2.x = o[nt][0] * inv0; v2.y = o[nt][1] * inv0;
            *(float2*)(orow + 8 * nt + 2 * t) = v2;
        }
    }
    if (qrow + 8 < NQ) {
        float* orow = out + ((size_t)b * NQ + qrow + 8) * DIM + h * 32;
        #pragma unroll
        for (int nt = 0; nt < 4; nt++) {
            float2 v2; v2.x = o[nt][2] * inv1; v2.y = o[nt][3] * inv1;
            *(float2*)(orow + 8 * nt + 2 * t) = v2;
        }
    }
}

extern "C" void kernel_launch(void* const* d_in, const int* in_sizes, int n_in,
                              void* d_out, int out_size) {
    const float* qkv        = (const float*)d_in[0];
    const float* mask       = (const float*)d_in[1];
    const float* bias_table = (const float*)d_in[2];
    const int*   rel_index  = (const int*)d_in[3];
    float* out = (float*)d_out;

    precompute_bm3<<<(BM3_TOTAL + 255) / 256, 256>>>(mask, bias_table, rel_index);
    window_attn_h16<<<BWIN * HN, 128>>>(qkv, out);
}